// round 4
// baseline (speedup 1.0000x reference)
#include <cuda_runtime.h>
#include <cstdint>

#define BSZ    256
#define BOND   5
#define NDIM   128
#define ATOM   64
#define UNITS  128
#define THREADS 512

// smem float-word pitches (conflict-free fragment access)
#define P_F    72    // F   [n=128][d=64]    B-op: (8*c4 + r4) % 32 distinct
#define P_ADJ  132   // adj [m=128][n=128]   A-op: (4*r4 + c4) % 32 distinct
#define P_K    136   // K   [d=64][u=128]    B-op: (8*c4 + r4) % 32 distinct
#define P_X1   68    // X1  [m=128][d=64]    A-op: (4*r4 + c4) % 32 distinct

// smem layout in float words: F | adj | K0 | K1 | X1
#define OFF_F    0
#define OFF_ADJ  (OFF_F   + NDIM * P_F)     // 9216
#define OFF_K0   (OFF_ADJ + NDIM * P_ADJ)   // 26112
#define OFF_K1   (OFF_K0  + ATOM * P_K)     // 34816
#define OFF_X1   (OFF_K1  + ATOM * P_K)     // 43520
#define SMEM_WORDS (OFF_X1 + NDIM * P_X1)   // 52224
#define SMEM_BYTES (SMEM_WORDS * 4)         // 208896 (< 227KB max dynamic)

__device__ __forceinline__ float f2tf32f(float f) {
    uint32_t u;
    asm("cvt.rna.tf32.f32 %0, %1;" : "=r"(u) : "f"(f));
    return __uint_as_float(u);
}

__device__ __forceinline__ void mma_tf32(float c[4], const uint32_t a[4], const uint32_t b[2]) {
    asm volatile(
        "mma.sync.aligned.m16n8k8.row.col.f32.tf32.tf32.f32 "
        "{%0,%1,%2,%3}, {%4,%5,%6,%7}, {%8,%9}, {%0,%1,%2,%3};"
        : "+f"(c[0]), "+f"(c[1]), "+f"(c[2]), "+f"(c[3])
        : "r"(a[0]), "r"(a[1]), "r"(a[2]), "r"(a[3]), "r"(b[0]), "r"(b[1]));
}

__device__ __forceinline__ uint32_t smem_u32(const void* p) {
    uint32_t a;
    asm("{ .reg .u64 t; cvta.to.shared.u64 t, %1; cvt.u32.u64 %0, t; }" : "=r"(a) : "l"(p));
    return a;
}
__device__ __forceinline__ void cpa16(uint32_t s, const float4* g) {
    asm volatile("cp.async.cg.shared.global [%0], [%1], 16;" :: "r"(s), "l"(g) : "memory");
}
#define CP_COMMIT() asm volatile("cp.async.commit_group;" ::: "memory")
#define CP_WAIT0()  asm volatile("cp.async.wait_group 0;" ::: "memory")

// ---- cp.async staging (raw fp32; tf32 conversion happens at fragment load) ----
__device__ __forceinline__ void stage_adj(uint32_t sAdjB, const float4* src, int tid) {
    #pragma unroll
    for (int t = 0; t < 8; t++) {
        int i = tid + t * THREADS;          // 0..4095
        int m = i >> 5, n4 = i & 31;
        cpa16(sAdjB + (uint32_t)(m * P_ADJ + n4 * 4) * 4u, src + i);
    }
}
__device__ __forceinline__ void stage_K(uint32_t sKB, const float4* src, int tid) {
    #pragma unroll
    for (int t = 0; t < 4; t++) {
        int i = tid + t * THREADS;          // 0..2047
        int dd = i >> 5, u4 = i & 31;
        cpa16(sKB + (uint32_t)(dd * P_K + u4 * 4) * 4u, src + i);
    }
}
__device__ __forceinline__ void stage_F(uint32_t sFB, const float4* src, int tid) {
    #pragma unroll
    for (int t = 0; t < 4; t++) {
        int i = tid + t * THREADS;          // 0..2047
        int node = i >> 4, a4 = i & 15;
        cpa16(sFB + (uint32_t)(node * P_F + a4 * 4) * 4u, src + i);
    }
}

__global__ void __launch_bounds__(THREADS, 1)
rgc_kernel(const float* __restrict__ adjacency,
           const float* __restrict__ features,
           const float* __restrict__ kern,
           float* __restrict__ out) {
    extern __shared__ float sm[];
    float* sF   = sm + OFF_F;
    float* sAdj = sm + OFF_ADJ;
    float* sK[2] = { sm + OFF_K0, sm + OFF_K1 };
    float* sX1  = sm + OFF_X1;

    const uint32_t smb   = smem_u32(sm);
    const uint32_t sFB   = smb + OFF_F * 4u;
    const uint32_t sAdjB = smb + OFF_ADJ * 4u;
    const uint32_t sKB[2] = { smb + OFF_K0 * 4u, smb + OFF_K1 * 4u };

    const int tid = threadIdx.x;
    const int wid = tid >> 5;
    const int lid = tid & 31;
    const int r4  = lid >> 2;
    const int c4  = lid & 3;
    const int b   = blockIdx.x;

    const int m0 = (wid & 3) * 32;       // M tile base (both GEMMs)
    const int d0 = (wid >> 2) * 16;      // GEMM1 N (=atom) tile base
    const int u0 = (wid >> 2) * 32;      // GEMM2 N (=units) tile base

    const float4* adj4  = reinterpret_cast<const float4*>(adjacency);
    const float4* ker4  = reinterpret_cast<const float4*>(kern);
    const float4* feat4 = reinterpret_cast<const float4*>(features);

    // ---- prologue: F + adj(0) + K(0) via cp.async ----
    stage_F(sFB, feat4 + (size_t)b * 2048, tid);
    stage_adj(sAdjB, adj4 + (size_t)(b * BOND) * 4096, tid);
    stage_K(sKB[0], ker4 + (size_t)(b * BOND) * 2048, tid);
    CP_COMMIT();

    // GEMM2 accumulator (persists across bonds): 32x32 tile per warp
    float acc2[2][4][4];
    #pragma unroll
    for (int mt = 0; mt < 2; mt++)
        #pragma unroll
        for (int nt = 0; nt < 4; nt++)
            #pragma unroll
            for (int k = 0; k < 4; k++) acc2[mt][nt][k] = 0.0f;

    CP_WAIT0();
    __syncthreads();

    for (int e = 0; e < BOND; e++) {
        // ---- GEMM1: X1[m,d] = sum_n adj[m,n]*F[n,d]; warp tile 32x16 ----
        float acc1[2][2][4];
        #pragma unroll
        for (int mt = 0; mt < 2; mt++)
            #pragma unroll
            for (int nt = 0; nt < 2; nt++)
                #pragma unroll
                for (int k = 0; k < 4; k++) acc1[mt][nt][k] = 0.0f;

        #pragma unroll 4
        for (int ks = 0; ks < 16; ks++) {
            const int k0 = ks * 8;
            uint32_t a[2][4];
            #pragma unroll
            for (int mt = 0; mt < 2; mt++) {
                const float* pa = sAdj + (m0 + mt * 16 + r4) * P_ADJ + k0 + c4;
                a[mt][0] = __float_as_uint(f2tf32f(pa[0]));
                a[mt][1] = __float_as_uint(f2tf32f(pa[8 * P_ADJ]));
                a[mt][2] = __float_as_uint(f2tf32f(pa[4]));
                a[mt][3] = __float_as_uint(f2tf32f(pa[8 * P_ADJ + 4]));
            }
            uint32_t bf[2][2];
            #pragma unroll
            for (int nt = 0; nt < 2; nt++) {
                const float* pb = sF + (k0 + c4) * P_F + d0 + nt * 8 + r4;
                bf[nt][0] = __float_as_uint(f2tf32f(pb[0]));
                bf[nt][1] = __float_as_uint(f2tf32f(pb[4 * P_F]));
            }
            #pragma unroll
            for (int mt = 0; mt < 2; mt++)
                #pragma unroll
                for (int nt = 0; nt < 2; nt++)
                    mma_tf32(acc1[mt][nt], a[mt], bf[nt]);
        }

        // ---- X1 -> smem (raw fp32; tf32-rounded at GEMM2 fragment load) ----
        #pragma unroll
        for (int mt = 0; mt < 2; mt++) {
            #pragma unroll
            for (int nt = 0; nt < 2; nt++) {
                const int row = m0 + mt * 16 + r4;
                const int col = d0 + nt * 8 + 2 * c4;
                *reinterpret_cast<float2*>(sX1 + row * P_X1 + col) =
                    make_float2(acc1[mt][nt][0], acc1[mt][nt][1]);
                *reinterpret_cast<float2*>(sX1 + (row + 8) * P_X1 + col) =
                    make_float2(acc1[mt][nt][2], acc1[mt][nt][3]);
            }
        }
        __syncthreads();   // X1 visible; adj(e) fully consumed

        // ---- prefetch bond e+1 (overlaps GEMM2) ----
        if (e + 1 < BOND) {
            stage_adj(sAdjB, adj4 + (size_t)(b * BOND + e + 1) * 4096, tid);
            stage_K(sKB[(e + 1) & 1], ker4 + (size_t)(b * BOND + e + 1) * 2048, tid);
            CP_COMMIT();
        }

        // ---- GEMM2: OUT[m,u] += sum_d X1[m,d]*K[d,u]; warp tile 32x32 ----
        const float* sKe = sK[e & 1];
        #pragma unroll 2
        for (int ks = 0; ks < 8; ks++) {
            const int k0 = ks * 8;
            uint32_t a[2][4];
            #pragma unroll
            for (int mt = 0; mt < 2; mt++) {
                const float* pa = sX1 + (m0 + mt * 16 + r4) * P_X1 + k0 + c4;
                a[mt][0] = __float_as_uint(f2tf32f(pa[0]));
                a[mt][1] = __float_as_uint(f2tf32f(pa[8 * P_X1]));
                a[mt][2] = __float_as_uint(f2tf32f(pa[4]));
                a[mt][3] = __float_as_uint(f2tf32f(pa[8 * P_X1 + 4]));
            }
            uint32_t bf[4][2];
            #pragma unroll
            for (int nt = 0; nt < 4; nt++) {
                const float* pb = sKe + (k0 + c4) * P_K + u0 + nt * 8 + r4;
                bf[nt][0] = __float_as_uint(f2tf32f(pb[0]));
                bf[nt][1] = __float_as_uint(f2tf32f(pb[4 * P_K]));
            }
            #pragma unroll
            for (int mt = 0; mt < 2; mt++)
                #pragma unroll
                for (int nt = 0; nt < 4; nt++)
                    mma_tf32(acc2[mt][nt], a[mt], bf[nt]);
        }

        if (e + 1 < BOND) CP_WAIT0();
        __syncthreads();   // adj/K(e+1) visible; X1 reads complete
    }

    // ---- epilogue: ReLU + store OUT[b][m][u] ----
    float* ob = out + (size_t)b * (NDIM * UNITS);
    #pragma unroll
    for (int mt = 0; mt < 2; mt++) {
        #pragma unroll
        for (int nt = 0; nt < 4; nt++) {
            const int row = m0 + mt * 16 + r4;
            const int col = u0 + nt * 8 + 2 * c4;
            float2 v0 = make_float2(fmaxf(acc2[mt][nt][0], 0.0f), fmaxf(acc2[mt][nt][1], 0.0f));
            float2 v1 = make_float2(fmaxf(acc2[mt][nt][2], 0.0f), fmaxf(acc2[mt][nt][3], 0.0f));
            *reinterpret_cast<float2*>(ob + row * UNITS + col)       = v0;
            *reinterpret_cast<float2*>(ob + (row + 8) * UNITS + col) = v1;
        }
    }
}

extern "C" void kernel_launch(void* const* d_in, const int* in_sizes, int n_in,
                              void* d_out, int out_size) {
    const float* adj  = nullptr;
    const float* feat = nullptr;
    const float* ker  = nullptr;
    for (int i = 0; i < n_in; i++) {
        if      (in_sizes[i] == BSZ * BOND * NDIM * NDIM)  adj  = (const float*)d_in[i];
        else if (in_sizes[i] == BSZ * NDIM * ATOM)         feat = (const float*)d_in[i];
        else if (in_sizes[i] == BSZ * BOND * ATOM * UNITS) ker  = (const float*)d_in[i];
    }
    if (!adj)  adj  = (const float*)d_in[0];
    if (!feat) feat = (const float*)d_in[1];
    if (!ker)  ker  = (const float*)d_in[2];

    cudaFuncSetAttribute(rgc_kernel, cudaFuncAttributeMaxDynamicSharedMemorySize, SMEM_BYTES);
    rgc_kernel<<<BSZ, THREADS, SMEM_BYTES>>>(adj, feat, ker, (float*)d_out);
}

// round 5
// speedup vs baseline: 1.3112x; 1.3112x over previous
#include <cuda_runtime.h>
#include <cstdint>

#define BSZ    256
#define BOND   5
#define NDIM   128
#define ATOM   64
#define UNITS  128
#define THREADS 256

// smem float-word pitches (conflict-free fragment access; pitch % 32 == 4 or 8)
#define P_F    72    // F   [n=128][d=64]
#define P_ADJ  132   // adj [m=128][n=128]
#define P_K    136   // K   [d=64][u=128]
#define P_X1   68    // X1  [m=128][d=64]

// smem layout in float words: F | adj | K0 | K1 | X1
#define OFF_F    0
#define OFF_ADJ  (OFF_F   + NDIM * P_F)     // 9216
#define OFF_K0   (OFF_ADJ + NDIM * P_ADJ)   // 26112
#define OFF_K1   (OFF_K0  + ATOM * P_K)     // 34816
#define OFF_X1   (OFF_K1  + ATOM * P_K)     // 43520
#define SMEM_WORDS (OFF_X1 + NDIM * P_X1)   // 52224
#define SMEM_BYTES (SMEM_WORDS * 4)         // 208896 (< 227KB)

__device__ __forceinline__ float f2tf32f(float f) {
    uint32_t u;
    asm("cvt.rna.tf32.f32 %0, %1;" : "=r"(u) : "f"(f));
    return __uint_as_float(u);
}

__device__ __forceinline__ void mma_tf32(float c[4], const uint32_t a[4], const uint32_t b[2]) {
    asm volatile(
        "mma.sync.aligned.m16n8k8.row.col.f32.tf32.tf32.f32 "
        "{%0,%1,%2,%3}, {%4,%5,%6,%7}, {%8,%9}, {%0,%1,%2,%3};"
        : "+f"(c[0]), "+f"(c[1]), "+f"(c[2]), "+f"(c[3])
        : "r"(a[0]), "r"(a[1]), "r"(a[2]), "r"(a[3]), "r"(b[0]), "r"(b[1]));
}

__device__ __forceinline__ uint32_t smem_u32(const void* p) {
    uint32_t a;
    asm("{ .reg .u64 t; cvta.to.shared.u64 t, %1; cvt.u32.u64 %0, t; }" : "=r"(a) : "l"(p));
    return a;
}
__device__ __forceinline__ void cpa16(uint32_t s, const float4* g) {
    asm volatile("cp.async.cg.shared.global [%0], [%1], 16;" :: "r"(s), "l"(g) : "memory");
}
#define CP_COMMIT() asm volatile("cp.async.commit_group;" ::: "memory")
template<int N> __device__ __forceinline__ void cp_wait() {
    asm volatile("cp.async.wait_group %0;" :: "n"(N) : "memory");
}

__global__ void __launch_bounds__(THREADS, 1)
rgc_kernel(const float* __restrict__ adjacency,
           const float* __restrict__ features,
           const float* __restrict__ kern,
           float* __restrict__ out) {
    extern __shared__ float sm[];
    float* sF   = sm + OFF_F;
    float* sAdj = sm + OFF_ADJ;
    float* sK0  = sm + OFF_K0;
    float* sK1  = sm + OFF_K1;
    float* sX1  = sm + OFF_X1;

    const uint32_t smb   = smem_u32(sm);
    const uint32_t sFB   = smb + OFF_F * 4u;
    const uint32_t sAdjB = smb + OFF_ADJ * 4u;
    const uint32_t sK0B  = smb + OFF_K0 * 4u;
    const uint32_t sK1B  = smb + OFF_K1 * 4u;

    const int tid = threadIdx.x;
    const int wid = tid >> 5;
    const int lid = tid & 31;
    const int r4  = lid >> 2;
    const int c4  = lid & 3;
    const int b   = blockIdx.x;

    const int m0 = (wid & 3) * 32;       // M tile base (both GEMMs)
    const int d0 = (wid >> 2) * 32;      // GEMM1 N (=atom) tile base
    const int u0 = (wid >> 2) * 64;      // GEMM2 N (=units) tile base

    const float4* adj4  = reinterpret_cast<const float4*>(adjacency);
    const float4* ker4  = reinterpret_cast<const float4*>(kern);
    const float4* feat4 = reinterpret_cast<const float4*>(features);
    const float4* adjB  = adj4 + (size_t)(b * BOND) * 4096;
    const float4* kerB  = ker4 + (size_t)(b * BOND) * 2048;

    // stage one 32-col k-chunk of adjacency (1024 float4 = 4 iters)
    auto stage_adj_chunk = [&](const float4* src, int c) {
        #pragma unroll
        for (int t = 0; t < 4; t++) {
            int i = tid + t * THREADS;          // 0..1023
            int m = i >> 3, j = i & 7;
            cpa16(sAdjB + (uint32_t)(m * P_ADJ + (c * 8 + j) * 4) * 4u,
                  src + m * 32 + c * 8 + j);
        }
    };
    auto stage_K = [&](uint32_t dstB, const float4* src) {
        #pragma unroll
        for (int t = 0; t < 8; t++) {
            int i = tid + t * THREADS;          // 0..2047
            int dd = i >> 5, u4 = i & 31;
            cpa16(dstB + (uint32_t)(dd * P_K + u4 * 4) * 4u, src + i);
        }
    };

    // ---- prologue: group0=[F + adj0.c0], then adj0.c1-3, then K0 (5 groups) ----
    {
        const float4* srcF = feat4 + (size_t)b * 2048;
        #pragma unroll
        for (int t = 0; t < 8; t++) {
            int i = tid + t * THREADS;
            int node = i >> 4, a4 = i & 15;
            cpa16(sFB + (uint32_t)(node * P_F + a4 * 4) * 4u, srcF + i);
        }
        stage_adj_chunk(adjB, 0); CP_COMMIT();
        stage_adj_chunk(adjB, 1); CP_COMMIT();
        stage_adj_chunk(adjB, 2); CP_COMMIT();
        stage_adj_chunk(adjB, 3); CP_COMMIT();
        stage_K(sK0B, kerB);      CP_COMMIT();
    }

    float acc2[2][8][4];
    #pragma unroll
    for (int mt = 0; mt < 2; mt++)
        #pragma unroll
        for (int nt = 0; nt < 8; nt++)
            #pragma unroll
            for (int k = 0; k < 4; k++) acc2[mt][nt][k] = 0.0f;

    // GEMM1 body over one 32-wide k-chunk (4 mma K-steps)
    float acc1[2][4][4];
    auto g1_chunk = [&](int c) {
        #pragma unroll
        for (int ks4 = 0; ks4 < 4; ks4++) {
            const int k0 = c * 32 + ks4 * 8;
            uint32_t a[2][4];
            #pragma unroll
            for (int mt = 0; mt < 2; mt++) {
                const float* pa = sAdj + (m0 + mt * 16 + r4) * P_ADJ + k0 + c4;
                // adjacency: raw fp32 bits (HW tf32 truncation; values in [0,1))
                a[mt][0] = __float_as_uint(pa[0]);
                a[mt][1] = __float_as_uint(pa[8 * P_ADJ]);
                a[mt][2] = __float_as_uint(pa[4]);
                a[mt][3] = __float_as_uint(pa[8 * P_ADJ + 4]);
            }
            uint32_t bf[4][2];
            #pragma unroll
            for (int nt = 0; nt < 4; nt++) {
                const float* pb = sF + (k0 + c4) * P_F + d0 + nt * 8 + r4;
                bf[nt][0] = __float_as_uint(f2tf32f(pb[0]));
                bf[nt][1] = __float_as_uint(f2tf32f(pb[4 * P_F]));
            }
            #pragma unroll
            for (int mt = 0; mt < 2; mt++)
                #pragma unroll
                for (int nt = 0; nt < 4; nt++)
                    mma_tf32(acc1[mt][nt], a[mt], bf[nt]);
        }
    };

    #pragma unroll 1
    for (int e = 0; e < BOND; e++) {
        #pragma unroll
        for (int mt = 0; mt < 2; mt++)
            #pragma unroll
            for (int nt = 0; nt < 4; nt++)
                #pragma unroll
                for (int k = 0; k < 4; k++) acc1[mt][nt][k] = 0.0f;

        // ---- GEMM1, chunk-pipelined against in-flight cp.async groups ----
        cp_wait<4>(); __syncthreads(); g1_chunk(0);
        cp_wait<3>(); __syncthreads(); g1_chunk(1);
        cp_wait<2>(); __syncthreads(); g1_chunk(2);
        cp_wait<1>(); __syncthreads(); g1_chunk(3);

        // ---- X1 -> smem, pre-rounded to tf32 (A operand of GEMM2) ----
        #pragma unroll
        for (int mt = 0; mt < 2; mt++) {
            #pragma unroll
            for (int nt = 0; nt < 4; nt++) {
                const int row = m0 + mt * 16 + r4;
                const int col = d0 + nt * 8 + 2 * c4;
                *reinterpret_cast<float2*>(sX1 + row * P_X1 + col) =
                    make_float2(f2tf32f(acc1[mt][nt][0]), f2tf32f(acc1[mt][nt][1]));
                *reinterpret_cast<float2*>(sX1 + (row + 8) * P_X1 + col) =
                    make_float2(f2tf32f(acc1[mt][nt][2]), f2tf32f(acc1[mt][nt][3]));
            }
        }
        cp_wait<0>();        // K(e) landed (adj(e) already consumed)
        __syncthreads();     // X1 visible; all GEMM1 reads of adj done

        // ---- prefetch bond e+1 (5 groups; fly during GEMM2) ----
        if (e + 1 < BOND) {
            const float4* adjN = adjB + (size_t)(e + 1) * 4096;
            stage_adj_chunk(adjN, 0); CP_COMMIT();
            stage_adj_chunk(adjN, 1); CP_COMMIT();
            stage_adj_chunk(adjN, 2); CP_COMMIT();
            stage_adj_chunk(adjN, 3); CP_COMMIT();
            stage_K((e & 1) ? sK0B : sK1B, kerB + (size_t)(e + 1) * 2048); CP_COMMIT();
        }

        // ---- GEMM2: OUT[m,u] += sum_d X1[m,d]*K[d,u]; warp tile 32x64 ----
        const float* sKe = (e & 1) ? sK1 : sK0;
        #pragma unroll 2
        for (int ks = 0; ks < 8; ks++) {
            const int k0 = ks * 8;
            uint32_t a[2][4];
            #pragma unroll
            for (int mt = 0; mt < 2; mt++) {
                const float* pa = sX1 + (m0 + mt * 16 + r4) * P_X1 + k0 + c4;
                a[mt][0] = __float_as_uint(pa[0]);      // already tf32-rounded
                a[mt][1] = __float_as_uint(pa[8 * P_X1]);
                a[mt][2] = __float_as_uint(pa[4]);
                a[mt][3] = __float_as_uint(pa[8 * P_X1 + 4]);
            }
            uint32_t bf[8][2];
            #pragma unroll
            for (int nt = 0; nt < 8; nt++) {
                const float* pb = sKe + (k0 + c4) * P_K + u0 + nt * 8 + r4;
                bf[nt][0] = __float_as_uint(f2tf32f(pb[0]));
                bf[nt][1] = __float_as_uint(f2tf32f(pb[4 * P_K]));
            }
            #pragma unroll
            for (int mt = 0; mt < 2; mt++)
                #pragma unroll
                for (int nt = 0; nt < 8; nt++)
                    mma_tf32(acc2[mt][nt], a[mt], bf[nt]);
        }
        // no end-of-bond sync: next bond's chunk-0 barrier orders X1/adj reuse
    }

    // ---- epilogue: ReLU + store OUT[b][m][u] ----
    float* ob = out + (size_t)b * (NDIM * UNITS);
    #pragma unroll
    for (int mt = 0; mt < 2; mt++) {
        #pragma unroll
        for (int nt = 0; nt < 8; nt++) {
            const int row = m0 + mt * 16 + r4;
            const int col = u0 + nt * 8 + 2 * c4;
            float2 v0 = make_float2(fmaxf(acc2[mt][nt][0], 0.0f), fmaxf(acc2[mt][nt][1], 0.0f));
            float2 v1 = make_float2(fmaxf(acc2[mt][nt][2], 0.0f), fmaxf(acc2[mt][nt][3], 0.0f));
            *reinterpret_cast<float2*>(ob + row * UNITS + col)       = v0;
            *reinterpret_cast<float2*>(ob + (row + 8) * UNITS + col) = v1;
        }
    }
}

extern "C" void kernel_launch(void* const* d_in, const int* in_sizes, int n_in,
                              void* d_out, int out_size) {
    const float* adj  = nullptr;
    const float* feat = nullptr;
    const float* ker  = nullptr;
    for (int i = 0; i < n_in; i++) {
        if      (in_sizes[i] == BSZ * BOND * NDIM * NDIM)  adj  = (const float*)d_in[i];
        else if (in_sizes[i] == BSZ * NDIM * ATOM)         feat = (const float*)d_in[i];
        else if (in_sizes[i] == BSZ * BOND * ATOM * UNITS) ker  = (const float*)d_in[i];
    }
    if (!adj)  adj  = (const float*)d_in[0];
    if (!feat) feat = (const float*)d_in[1];
    if (!ker)  ker  = (const float*)d_in[2];

    cudaFuncSetAttribute(rgc_kernel, cudaFuncAttributeMaxDynamicSharedMemorySize, SMEM_BYTES);
    rgc_kernel<<<BSZ, THREADS, SMEM_BYTES>>>(adj, feat, ker, (float*)d_out);
}